// round 11
// baseline (speedup 1.0000x reference)
#include <cuda_runtime.h>
#include <cuda_fp16.h>
#include <math.h>
#include <stdint.h>
#include <string.h>

#define NH   16
#define DHD  64
#define NB   4
#define LQ   1024
#define LK   2048
#define DM   1024
#define MAXPOS 2048
#define STR  72    // fp16 smem row stride (144B)
#define SSTR 136   // S23 fp16 stride (even: 4B-aligned vector stores)

// ---------------- static device scratch ----------------
__device__ __half g_Q[(size_t)NB*NH*LQ*DHD];
__device__ __half g_K[(size_t)NB*NH*LK*DHD];
__device__ __half g_Vt[(size_t)NB*NH*DHD*LK];   // [b,h][d][r]
__device__ __half g_E[(size_t)(2*MAXPOS-1)*DHD];

__device__ __half g_Xq[(size_t)NB*LQ*DM];
__device__ __half g_Xk[(size_t)NB*LK*DM];
__device__ __half g_W[3][(size_t)DM*DM];

// ============================ helpers ============================
__device__ __forceinline__ uint32_t smem_u32(const void* p) {
    uint32_t a;
    asm("{ .reg .u64 t; cvta.to.shared.u64 t, %1; cvt.u32.u64 %0, t; }"
        : "=r"(a) : "l"(p));
    return a;
}
__device__ __forceinline__ void cp_async16(uint32_t saddr, const void* gaddr) {
    asm volatile("cp.async.cg.shared.global [%0], [%1], 16;" :: "r"(saddr), "l"(gaddr));
}
__device__ __forceinline__ void cp_commit() { asm volatile("cp.async.commit_group;"); }
template <int N>
__device__ __forceinline__ void cp_wait() { asm volatile("cp.async.wait_group %0;" :: "n"(N)); }

__device__ __forceinline__ void mma_f16(float* c, const uint32_t* a, const uint32_t* b) {
    asm volatile(
        "mma.sync.aligned.m16n8k16.row.col.f32.f16.f16.f32 "
        "{%0,%1,%2,%3}, {%4,%5,%6,%7}, {%8,%9}, {%0,%1,%2,%3};"
        : "+f"(c[0]), "+f"(c[1]), "+f"(c[2]), "+f"(c[3])
        : "r"(a[0]), "r"(a[1]), "r"(a[2]), "r"(a[3]), "r"(b[0]), "r"(b[1]));
}
__device__ __forceinline__ uint32_t hpack(float x, float y) {
    __half2 h = __floats2half2_rn(x, y);
    uint32_t u; memcpy(&u, &h, 4); return u;
}

// =================================================================================
__global__ void convh_kernel(const float* __restrict__ x,
                             __half* __restrict__ y, int n4)
{
    int i = blockIdx.x * blockDim.x + threadIdx.x;
    if (i >= n4) return;
    float4 v = ((const float4*)x)[i];
    ((uint32_t*)y)[2*i]   = hpack(v.x, v.y);
    ((uint32_t*)y)[2*i+1] = hpack(v.z, v.w);
}

// =================================================================================
// Projection GEMM, fp16 single-pass (proven R9)
// =================================================================================
#define BK      32
#define KS_STR  40
#define TILE_HF (128 * KS_STR)
#define STAGE_HF (2 * TILE_HF)
#define PROJ_SMEM_BYTES (2 * STAGE_HF * 2)

__global__ __launch_bounds__(256)
void proj_tc(const __half* __restrict__ A_g, const __half* __restrict__ B_g,
             const float* __restrict__ bias,
             __half* __restrict__ outH, int L, int mode)
{
    extern __shared__ __half smem[];
    const uint32_t smem_b = smem_u32(smem);
    const int t = threadIdx.x, lane = t & 31;
    const int wid = t >> 5, g = lane >> 2, t4 = lane & 3;
    const int wm0 = (wid & 3) * 32, wn0 = (wid >> 2) * 64;
    const int m0 = blockIdx.x * 128, n0 = blockIdx.y * 128;
    const int c0 = t * 2;
    const int row0 = c0 >> 2, seg0 = c0 & 3;
    const int row1 = (c0 + 1) >> 2, seg1 = (c0 + 1) & 3;
    const int NS = DM / BK;

    auto load_stage = [&](int kc) {
        const int k0 = kc * BK;
        const uint32_t sb = smem_b + (uint32_t)(kc & 1) * STAGE_HF * 2;
        const uint32_t so0 = (uint32_t)(row0 * KS_STR + seg0 * 8) * 2;
        const uint32_t so1 = (uint32_t)(row1 * KS_STR + seg1 * 8) * 2;
        cp_async16(sb + so0, A_g + (size_t)(m0 + row0) * DM + k0 + seg0 * 8);
        cp_async16(sb + so1, A_g + (size_t)(m0 + row1) * DM + k0 + seg1 * 8);
        cp_async16(sb + TILE_HF * 2 + so0, B_g + (size_t)(n0 + row0) * DM + k0 + seg0 * 8);
        cp_async16(sb + TILE_HF * 2 + so1, B_g + (size_t)(n0 + row1) * DM + k0 + seg1 * 8);
        cp_commit();
    };

    float acc[2][8][4];
#pragma unroll
    for (int i = 0; i < 2; i++)
#pragma unroll
        for (int j = 0; j < 8; j++)
#pragma unroll
            for (int q = 0; q < 4; q++) acc[i][j][q] = 0.0f;

    load_stage(0);
    for (int kc = 0; kc < NS; kc++) {
        if (kc + 1 < NS) { load_stage(kc + 1); cp_wait<1>(); }
        else             { cp_wait<0>(); }
        __syncthreads();
        const __half* sA = smem + (size_t)(kc & 1) * STAGE_HF;
        const __half* sB = sA + TILE_HF;
#pragma unroll
        for (int ks = 0; ks < BK; ks += 16) {
            uint32_t aF[2][4], bF[8][2];
            const int kk = ks + t4 * 2;
#pragma unroll
            for (int i = 0; i < 2; i++) {
                const int r = wm0 + i * 16 + g;
                aF[i][0] = *(const uint32_t*)&sA[r * KS_STR + kk];
                aF[i][1] = *(const uint32_t*)&sA[(r + 8) * KS_STR + kk];
                aF[i][2] = *(const uint32_t*)&sA[r * KS_STR + kk + 8];
                aF[i][3] = *(const uint32_t*)&sA[(r + 8) * KS_STR + kk + 8];
            }
#pragma unroll
            for (int j = 0; j < 8; j++) {
                const int n = wn0 + j * 8 + g;
                bF[j][0] = *(const uint32_t*)&sB[n * KS_STR + kk];
                bF[j][1] = *(const uint32_t*)&sB[n * KS_STR + kk + 8];
            }
#pragma unroll
            for (int i = 0; i < 2; i++)
#pragma unroll
                for (int j = 0; j < 8; j++)
                    mma_f16(acc[i][j], aF[i], bF[j]);
        }
        __syncthreads();
    }
#pragma unroll
    for (int i = 0; i < 2; i++)
#pragma unroll
        for (int j = 0; j < 8; j++) {
            const int cc = n0 + wn0 + j * 8 + t4 * 2;
            const int hh = cc >> 6, dh = cc & 63;
            const float b0 = __ldg(&bias[cc]), b1 = __ldg(&bias[cc + 1]);
#pragma unroll
            for (int rr = 0; rr < 2; rr++) {
                const int r = m0 + wm0 + i * 16 + g + rr * 8;
                const int bidx = r / L, l = r - bidx * L;
                const float f0 = acc[i][j][rr * 2 + 0] + b0;
                const float f1 = acc[i][j][rr * 2 + 1] + b1;
                if (mode == 0) {
                    const size_t base = ((size_t)(bidx * NH + hh) * L + l) * DHD + dh;
                    *(__half2*)&outH[base] = __floats2half2_rn(f0, f1);
                } else {
                    const size_t base = ((size_t)(bidx * NH + hh) * DHD + dh) * LK + l;
                    outH[base] = __float2half(f0);
                    outH[base + LK] = __float2half(f1);
                }
            }
        }
}

// =================================================================================
// Tensor-core attention: concurrent GEMM1||GEMM2 warp split (SSTR=136, aligned)
// =================================================================================
#define OFF_KH  0
#define OFF_VTH 9216
#define OFF_ES  18432
#define OFF_MS  36864
#define BUF_BYTES 37120

#define SM_S23 0
#define SM_SL  34816
#define SM_QH  52224
#define SM_BUF 61440
#define SM_PH  135680
#define SM_MR  144896
#define SM_LS  145152
#define SM_CS  145408
#define ATTN_SMEM 145664

__global__ __launch_bounds__(512, 1)
void attn_tc(const float* __restrict__ mask, float* __restrict__ out)
{
    extern __shared__ char smc[];
    const uint32_t sbu = smem_u32(smc);
    __half* S23 = (__half*)(smc + SM_S23);    // [128][SSTR=136]
    float* Sl = (float*)(smc + SM_SL);        // [64][68]
    __half* Qh = (__half*)(smc + SM_QH);
    __half* Ph = (__half*)(smc + SM_PH);
    float* Mr = (float*)(smc + SM_MR);
    float* Ls = (float*)(smc + SM_LS);
    float* Cs = (float*)(smc + SM_CS);

    const int t = threadIdx.x, lane = t & 31, w = t >> 5;   // 16 warps
    const int g = lane >> 2, t4 = lane & 3;
    const int sm0 = (w & 3) * 16, sn0 = (w >> 2) * 16;      // PV grid: 4m x 4n of 16x16
    const int l0 = blockIdx.x * 64, hd = blockIdx.y, b = blockIdx.z;

    // GEMM2 mapping for warps 8-15: 4m x 2n grid of 16x32 tiles
    const int w8   = w - 8;
    const int sm0g = (w8 & 3) * 16;
    const int sn0g = (w8 >> 2) * 32;

    const __half* Qg = g_Q + ((size_t)(b * NH + hd) * LQ + l0) * DHD;
    const __half* Kg = g_K + (size_t)(b * NH + hd) * LK * DHD;
    const __half* Vg = g_Vt + (size_t)(b * NH + hd) * DHD * LK;
    const float* mg = mask + (size_t)b * LK;

    // initial loads: Q + first buffer
    {
        const int row = t >> 3, c = t & 7;
        cp_async16(sbu + SM_QH + row * 144 + c * 16, Qg + row * DHD + c * 8);
        cp_async16(sbu + SM_BUF + OFF_KH + row * 144 + c * 16, Kg + (size_t)row * DHD + c * 8);
        cp_async16(sbu + SM_BUF + OFF_VTH + row * 144 + c * 16, Vg + (size_t)row * LK + c * 8);
        const int eb0 = l0 + (MAXPOS - 64);
#pragma unroll
        for (int i = 0; i < 2; i++) {
            int q = t + 512 * i;
            if (q < 127 * 8) {
                int rw = q >> 3, cc = q & 7;
                cp_async16(sbu + SM_BUF + OFF_ES + rw * 144 + cc * 16,
                           g_E + (size_t)(eb0 + rw) * DHD + cc * 8);
            }
        }
        if (t < 16) cp_async16(sbu + SM_BUF + OFF_MS + t * 16, mg + t * 4);
        cp_commit();
    }

    if (t < 64) { Mr[t] = -1e30f; Ls[t] = 0.f; }
    if (t < 72) {
        int bb = t / 36, wd = t % 36;
        *(uint32_t*)(smc + SM_BUF + bb * BUF_BYTES + OFF_ES + 127 * 144 + wd * 4) = 0u;
    }

    float O[2][4];
#pragma unroll
    for (int j = 0; j < 2; j++)
#pragma unroll
        for (int q = 0; q < 4; q++) O[j][q] = 0.f;

    // GEMM1 per-warp (warps 0-7): full 16-row m-block, 10 n-tile band in 2 passes
    const bool isQ = (w < 4);
    const int rk    = isQ ? 0 : (w - 4) * 16;
    const int arow0 = isQ ? w * 16 : rk;
    const int band0 = isQ ? w * 16 : 48 - rk;
    const int drow0 = isQ ? w * 16 : 64 + rk;

    for (int kt = 0; kt < LK / 64; kt++) {
        const int bb = kt & 1;
        const char* B = smc + SM_BUF + bb * BUF_BYTES;
        cp_wait<0>();
        __syncthreads();

        if (kt + 1 < LK / 64) {
            const int r1 = (kt + 1) * 64;
            const uint32_t P = sbu + SM_BUF + (bb ^ 1) * BUF_BYTES;
            const int row = t >> 3, c = t & 7;
            cp_async16(P + OFF_KH + row * 144 + c * 16, Kg + (size_t)(r1 + row) * DHD + c * 8);
            cp_async16(P + OFF_VTH + row * 144 + c * 16, Vg + (size_t)row * LK + r1 + c * 8);
            const int eb1 = l0 - r1 + (MAXPOS - 64);
#pragma unroll
            for (int i = 0; i < 2; i++) {
                int q = t + 512 * i;
                if (q < 127 * 8) {
                    int rw = q >> 3, cc = q & 7;
                    cp_async16(P + OFF_ES + rw * 144 + cc * 16,
                               g_E + (size_t)(eb1 + rw) * DHD + cc * 8);
                }
            }
            if (t < 16) cp_async16(P + OFF_MS + t * 16, mg + r1 + t * 4);
            cp_commit();
        }

        const __half* KhS = (const __half*)(B + OFF_KH);
        const __half* VhS = (const __half*)(B + OFF_VTH);
        const __half* EsS = (const __half*)(B + OFF_ES);
        const float* MsS = (const float*)(B + OFF_MS);

        float sc[4][4];   // GEMM2 accumulators (warps 8-15)

        if (w < 8) {
            // ---- GEMM1 (banded): one full m-block per warp, 2 passes of 5 n-tiles ----
            const __half* Ab = isQ ? Qh : KhS;
#pragma unroll
            for (int half = 0; half < 2; half++) {
                const int nt0 = band0 / 8 + half * 5;
                float ea[5][4];
#pragma unroll
                for (int j = 0; j < 5; j++)
#pragma unroll
                    for (int q = 0; q < 4; q++) ea[j][q] = 0.f;
#pragma unroll
                for (int k4 = 0; k4 < 4; k4++) {
                    const int kk = k4 * 16 + t4 * 2;
                    uint32_t af[4];
                    const int r = arow0 + g;
                    af[0] = *(const uint32_t*)&Ab[r * STR + kk];
                    af[1] = *(const uint32_t*)&Ab[(r + 8) * STR + kk];
                    af[2] = *(const uint32_t*)&Ab[r * STR + kk + 8];
                    af[3] = *(const uint32_t*)&Ab[(r + 8) * STR + kk + 8];
#pragma unroll
                    for (int j = 0; j < 5; j++) {
                        const int n = (nt0 + j) * 8 + g;
                        uint32_t bf2[2];
                        bf2[0] = *(const uint32_t*)&EsS[n * STR + kk];
                        bf2[1] = *(const uint32_t*)&EsS[n * STR + kk + 8];
                        mma_f16(ea[j], af, bf2);
                    }
                }
#pragma unroll
                for (int j = 0; j < 5; j++) {
                    const int m = drow0 + g, n = (nt0 + j) * 8 + t4 * 2;
                    *(uint32_t*)&S23[m * SSTR + n] = hpack(ea[j][0], ea[j][1]);
                    *(uint32_t*)&S23[(m + 8) * SSTR + n] = hpack(ea[j][2], ea[j][3]);
                }
            }
        } else {
            // ---- GEMM2: Q@K^T, 16x32 warp tiles ----
#pragma unroll
            for (int j = 0; j < 4; j++)
#pragma unroll
                for (int q = 0; q < 4; q++) sc[j][q] = 0.f;
#pragma unroll
            for (int k4 = 0; k4 < 4; k4++) {
                const int kk = k4 * 16 + t4 * 2;
                uint32_t aF[4];
                const int r = sm0g + g;
                aF[0] = *(const uint32_t*)&Qh[r * STR + kk];
                aF[1] = *(const uint32_t*)&Qh[(r + 8) * STR + kk];
                aF[2] = *(const uint32_t*)&Qh[r * STR + kk + 8];
                aF[3] = *(const uint32_t*)&Qh[(r + 8) * STR + kk + 8];
#pragma unroll
                for (int j = 0; j < 4; j++) {
                    const int n = sn0g + j * 8 + g;
                    uint32_t bF[2];
                    bF[0] = *(const uint32_t*)&KhS[n * STR + kk];
                    bF[1] = *(const uint32_t*)&KhS[n * STR + kk + 8];
                    mma_f16(sc[j], aF, bF);
                }
            }
        }
        __syncthreads();

        // ---- logits (warps 8-15): gather S23 diagonals + mask -> Sl ----
        if (w >= 8) {
#pragma unroll
            for (int j = 0; j < 4; j++) {
                const int ri = sn0g + j * 8 + t4 * 2;
#pragma unroll
                for (int ch = 0; ch < 2; ch++) {
                    const int li = sm0g + g + ch * 8;
                    const int nn = li - ri + 63;
                    float t0 = __half2float(S23[li * SSTR + nn])
                             + __half2float(S23[(64 + ri) * SSTR + nn]);
                    float t1 = __half2float(S23[li * SSTR + nn - 1])
                             + __half2float(S23[(65 + ri) * SSTR + nn - 1]);
                    float2 lv;
                    lv.x = (sc[j][ch * 2 + 0] + t0) * 0.125f + MsS[ri];
                    lv.y = (sc[j][ch * 2 + 1] + t1) * 0.125f + MsS[ri + 1];
                    *(float2*)&Sl[li * 68 + ri] = lv;
                }
            }
        }
        __syncthreads();

        // ---- online softmax (8 threads/row, all warps) ----
        {
            const int row = t >> 3, qq = t & 7;
            float v[8], mx = -1e30f;
#pragma unroll
            for (int c = 0; c < 8; c++) {
                v[c] = Sl[row * 68 + qq * 8 + c];
                mx = fmaxf(mx, v[c]);
            }
            mx = fmaxf(mx, __shfl_xor_sync(0xffffffffu, mx, 1));
            mx = fmaxf(mx, __shfl_xor_sync(0xffffffffu, mx, 2));
            mx = fmaxf(mx, __shfl_xor_sync(0xffffffffu, mx, 4));
            const float mold = Mr[row];
            const float mnew = fmaxf(mold, mx);
            const float corr = __expf(mold - mnew);
            float s = 0.f;
#pragma unroll
            for (int c = 0; c < 8; c++) { v[c] = __expf(v[c] - mnew); s += v[c]; }
            s += __shfl_xor_sync(0xffffffffu, s, 1);
            s += __shfl_xor_sync(0xffffffffu, s, 2);
            s += __shfl_xor_sync(0xffffffffu, s, 4);
            if (qq == 0) { Ls[row] = Ls[row] * corr + s; Mr[row] = mnew; Cs[row] = corr; }
#pragma unroll
            for (int c = 0; c < 8; c += 2)
                *(uint32_t*)&Ph[row * STR + qq * 8 + c] = hpack(v[c], v[c + 1]);
        }
        __syncthreads();

        // ---- PV (all 16 warps, 16x16 tiles) ----
        {
            const float c0 = Cs[sm0 + g];
            const float c1 = Cs[sm0 + g + 8];
#pragma unroll
            for (int j = 0; j < 2; j++) {
                O[j][0] *= c0; O[j][1] *= c0;
                O[j][2] *= c1; O[j][3] *= c1;
            }
        }
#pragma unroll
        for (int k4 = 0; k4 < 4; k4++) {
            const int kk = k4 * 16 + t4 * 2;
            uint32_t aF[4];
            const int r = sm0 + g;
            aF[0] = *(const uint32_t*)&Ph[r * STR + kk];
            aF[1] = *(const uint32_t*)&Ph[(r + 8) * STR + kk];
            aF[2] = *(const uint32_t*)&Ph[r * STR + kk + 8];
            aF[3] = *(const uint32_t*)&Ph[(r + 8) * STR + kk + 8];
#pragma unroll
            for (int j = 0; j < 2; j++) {
                const int d = sn0 + j * 8 + g;
                uint32_t bF[2];
                bF[0] = *(const uint32_t*)&VhS[d * STR + kk];
                bF[1] = *(const uint32_t*)&VhS[d * STR + kk + 8];
                mma_f16(O[j], aF, bF);
            }
        }
    }

    // ---- output [B, Lq, H*64] ----
#pragma unroll
    for (int ch = 0; ch < 2; ch++) {
        const int li = sm0 + g + ch * 8;
        const float inv = 1.0f / Ls[li];
#pragma unroll
        for (int j = 0; j < 2; j++) {
            const int d = sn0 + j * 8 + t4 * 2;
            float2 o;
            o.x = O[j][ch * 2 + 0] * inv;
            o.y = O[j][ch * 2 + 1] * inv;
            *(float2*)(out + ((size_t)(b * LQ) + l0 + li) * DM + hd * 64 + d) = o;
        }
    }
}

// =================================================================================
extern "C" void kernel_launch(void* const* d_in, const int* in_sizes, int n_in,
                              void* d_out, int out_size)
{
    const float* hidden   = (const float*)d_in[0];
    const float* q_hidden = (const float*)d_in[1];
    const float* mask     = (const float*)d_in[2];
    const float* Wq       = (const float*)d_in[3];
    const float* bq       = (const float*)d_in[4];
    const float* Wk       = (const float*)d_in[5];
    const float* bk       = (const float*)d_in[6];
    const float* Wv       = (const float*)d_in[7];
    const float* bv       = (const float*)d_in[8];
    const float* dist     = (const float*)d_in[9];
    float* out = (float*)d_out;

    __half *Qp, *Kp, *Vtp, *Ep, *Xq, *Xk, *Wp;
    cudaGetSymbolAddress((void**)&Qp,  g_Q);
    cudaGetSymbolAddress((void**)&Kp,  g_K);
    cudaGetSymbolAddress((void**)&Vtp, g_Vt);
    cudaGetSymbolAddress((void**)&Ep,  g_E);
    cudaGetSymbolAddress((void**)&Xq,  g_Xq);
    cudaGetSymbolAddress((void**)&Xk,  g_Xk);
    cudaGetSymbolAddress((void**)&Wp,  g_W);

    cudaFuncSetAttribute(proj_tc, cudaFuncAttributeMaxDynamicSharedMemorySize,
                         PROJ_SMEM_BYTES);
    cudaFuncSetAttribute(attn_tc, cudaFuncAttributeMaxDynamicSharedMemorySize,
                         ATTN_SMEM);

    const int nq = NB * LQ * DM / 4;
    const int nk = NB * LK * DM / 4;
    const int nw = DM * DM / 4;
    const int ne = (2 * MAXPOS - 1) * DHD / 4;
    convh_kernel<<<(nq + 255) / 256, 256>>>(q_hidden, Xq, nq);
    convh_kernel<<<(nk + 255) / 256, 256>>>(hidden,   Xk, nk);
    convh_kernel<<<(nw + 255) / 256, 256>>>(Wq, Wp + 0 * (size_t)DM * DM, nw);
    convh_kernel<<<(nw + 255) / 256, 256>>>(Wk, Wp + 1 * (size_t)DM * DM, nw);
    convh_kernel<<<(nw + 255) / 256, 256>>>(Wv, Wp + 2 * (size_t)DM * DM, nw);
    convh_kernel<<<(ne + 255) / 256, 256>>>(dist, Ep, ne);

    dim3 gq(NB * LQ / 128, DM / 128);
    dim3 gk(NB * LK / 128, DM / 128);
    proj_tc<<<gq, 256, PROJ_SMEM_BYTES>>>(Xq, Wp + 0 * (size_t)DM * DM, bq, Qp,  LQ, 0);
    proj_tc<<<gk, 256, PROJ_SMEM_BYTES>>>(Xk, Wp + 1 * (size_t)DM * DM, bk, Kp,  LK, 0);
    proj_tc<<<gk, 256, PROJ_SMEM_BYTES>>>(Xk, Wp + 2 * (size_t)DM * DM, bv, Vtp, LK, 1);

    dim3 ga(LQ / 64, NH, NB);
    attn_tc<<<ga, 512, ATTN_SMEM>>>(mask, out);
}

// round 12
// speedup vs baseline: 1.0706x; 1.0706x over previous
#include <cuda_runtime.h>
#include <cuda_fp16.h>
#include <math.h>
#include <stdint.h>
#include <string.h>

#define NH   16
#define DHD  64
#define NB   4
#define LQ   1024
#define LK   2048
#define DM   1024
#define MAXPOS 2048
#define STR  72    // fp16 smem row stride (144B)
#define SSTR 136   // S23 fp16 stride

// ---------------- static device scratch ----------------
__device__ __half g_Q[(size_t)NB*NH*LQ*DHD];
__device__ __half g_K[(size_t)NB*NH*LK*DHD];
__device__ __half g_Vt[(size_t)NB*NH*DHD*LK];   // [b,h][d][r]
__device__ __half g_E[(size_t)(2*MAXPOS-1)*DHD];

__device__ __half g_Xq[(size_t)NB*LQ*DM];
__device__ __half g_Xk[(size_t)NB*LK*DM];
__device__ __half g_W[3][(size_t)DM*DM];

// ============================ helpers ============================
__device__ __forceinline__ uint32_t smem_u32(const void* p) {
    uint32_t a;
    asm("{ .reg .u64 t; cvta.to.shared.u64 t, %1; cvt.u32.u64 %0, t; }"
        : "=r"(a) : "l"(p));
    return a;
}
__device__ __forceinline__ void cp_async16(uint32_t saddr, const void* gaddr) {
    asm volatile("cp.async.cg.shared.global [%0], [%1], 16;" :: "r"(saddr), "l"(gaddr));
}
__device__ __forceinline__ void cp_commit() { asm volatile("cp.async.commit_group;"); }
template <int N>
__device__ __forceinline__ void cp_wait() { asm volatile("cp.async.wait_group %0;" :: "n"(N)); }

__device__ __forceinline__ void mma_f16(float* c, const uint32_t* a, const uint32_t* b) {
    asm volatile(
        "mma.sync.aligned.m16n8k16.row.col.f32.f16.f16.f32 "
        "{%0,%1,%2,%3}, {%4,%5,%6,%7}, {%8,%9}, {%0,%1,%2,%3};"
        : "+f"(c[0]), "+f"(c[1]), "+f"(c[2]), "+f"(c[3])
        : "r"(a[0]), "r"(a[1]), "r"(a[2]), "r"(a[3]), "r"(b[0]), "r"(b[1]));
}
__device__ __forceinline__ uint32_t hpack(float x, float y) {
    __half2 h = __floats2half2_rn(x, y);
    uint32_t u; memcpy(&u, &h, 4); return u;
}

// =================================================================================
__global__ void convh_kernel(const float* __restrict__ x,
                             __half* __restrict__ y, int n4)
{
    int i = blockIdx.x * blockDim.x + threadIdx.x;
    if (i >= n4) return;
    float4 v = ((const float4*)x)[i];
    ((uint32_t*)y)[2*i]   = hpack(v.x, v.y);
    ((uint32_t*)y)[2*i+1] = hpack(v.z, v.w);
}

// =================================================================================
// Projection GEMM, fp16 single-pass (proven R9)
// =================================================================================
#define BK      32
#define KS_STR  40
#define TILE_HF (128 * KS_STR)
#define STAGE_HF (2 * TILE_HF)
#define PROJ_SMEM_BYTES (2 * STAGE_HF * 2)

__global__ __launch_bounds__(256)
void proj_tc(const __half* __restrict__ A_g, const __half* __restrict__ B_g,
             const float* __restrict__ bias,
             __half* __restrict__ outH, int L, int mode)
{
    extern __shared__ __half smem[];
    const uint32_t smem_b = smem_u32(smem);
    const int t = threadIdx.x, lane = t & 31;
    const int wid = t >> 5, g = lane >> 2, t4 = lane & 3;
    const int wm0 = (wid & 3) * 32, wn0 = (wid >> 2) * 64;
    const int m0 = blockIdx.x * 128, n0 = blockIdx.y * 128;
    const int c0 = t * 2;
    const int row0 = c0 >> 2, seg0 = c0 & 3;
    const int row1 = (c0 + 1) >> 2, seg1 = (c0 + 1) & 3;
    const int NS = DM / BK;

    auto load_stage = [&](int kc) {
        const int k0 = kc * BK;
        const uint32_t sb = smem_b + (uint32_t)(kc & 1) * STAGE_HF * 2;
        const uint32_t so0 = (uint32_t)(row0 * KS_STR + seg0 * 8) * 2;
        const uint32_t so1 = (uint32_t)(row1 * KS_STR + seg1 * 8) * 2;
        cp_async16(sb + so0, A_g + (size_t)(m0 + row0) * DM + k0 + seg0 * 8);
        cp_async16(sb + so1, A_g + (size_t)(m0 + row1) * DM + k0 + seg1 * 8);
        cp_async16(sb + TILE_HF * 2 + so0, B_g + (size_t)(n0 + row0) * DM + k0 + seg0 * 8);
        cp_async16(sb + TILE_HF * 2 + so1, B_g + (size_t)(n0 + row1) * DM + k0 + seg1 * 8);
        cp_commit();
    };

    float acc[2][8][4];
#pragma unroll
    for (int i = 0; i < 2; i++)
#pragma unroll
        for (int j = 0; j < 8; j++)
#pragma unroll
            for (int q = 0; q < 4; q++) acc[i][j][q] = 0.0f;

    load_stage(0);
    for (int kc = 0; kc < NS; kc++) {
        if (kc + 1 < NS) { load_stage(kc + 1); cp_wait<1>(); }
        else             { cp_wait<0>(); }
        __syncthreads();
        const __half* sA = smem + (size_t)(kc & 1) * STAGE_HF;
        const __half* sB = sA + TILE_HF;
#pragma unroll
        for (int ks = 0; ks < BK; ks += 16) {
            uint32_t aF[2][4], bF[8][2];
            const int kk = ks + t4 * 2;
#pragma unroll
            for (int i = 0; i < 2; i++) {
                const int r = wm0 + i * 16 + g;
                aF[i][0] = *(const uint32_t*)&sA[r * KS_STR + kk];
                aF[i][1] = *(const uint32_t*)&sA[(r + 8) * KS_STR + kk];
                aF[i][2] = *(const uint32_t*)&sA[r * KS_STR + kk + 8];
                aF[i][3] = *(const uint32_t*)&sA[(r + 8) * KS_STR + kk + 8];
            }
#pragma unroll
            for (int j = 0; j < 8; j++) {
                const int n = wn0 + j * 8 + g;
                bF[j][0] = *(const uint32_t*)&sB[n * KS_STR + kk];
                bF[j][1] = *(const uint32_t*)&sB[n * KS_STR + kk + 8];
            }
#pragma unroll
            for (int i = 0; i < 2; i++)
#pragma unroll
                for (int j = 0; j < 8; j++)
                    mma_f16(acc[i][j], aF[i], bF[j]);
        }
        __syncthreads();
    }
#pragma unroll
    for (int i = 0; i < 2; i++)
#pragma unroll
        for (int j = 0; j < 8; j++) {
            const int cc = n0 + wn0 + j * 8 + t4 * 2;
            const int hh = cc >> 6, dh = cc & 63;
            const float b0 = __ldg(&bias[cc]), b1 = __ldg(&bias[cc + 1]);
#pragma unroll
            for (int rr = 0; rr < 2; rr++) {
                const int r = m0 + wm0 + i * 16 + g + rr * 8;
                const int bidx = r / L, l = r - bidx * L;
                const float f0 = acc[i][j][rr * 2 + 0] + b0;
                const float f1 = acc[i][j][rr * 2 + 1] + b1;
                if (mode == 0) {
                    const size_t base = ((size_t)(bidx * NH + hh) * L + l) * DHD + dh;
                    *(__half2*)&outH[base] = __floats2half2_rn(f0, f1);
                } else {
                    const size_t base = ((size_t)(bidx * NH + hh) * DHD + dh) * LK + l;
                    outH[base] = __float2half(f0);
                    outH[base + LK] = __float2half(f1);
                }
            }
        }
}

// =================================================================================
// Tensor-core attention: in-register softmax, 4-warp PV, GEMM1 A-hoist
// =================================================================================
#define OFF_KH  0
#define OFF_VTH 9216
#define OFF_ES  18432
#define OFF_MS  36864
#define BUF_BYTES 37120

#define SM_S23 0
#define SM_QH  34816
#define SM_BUF 44032
#define SM_PH  118272
#define SM_PM  127488
#define SM_PS  128000
#define SM_MR  128512   // double-buffered [2][64]
#define SM_LS  129024   // double-buffered [2][64]
#define SM_CS  129536
#define ATTN_SMEM 129792

__global__ __launch_bounds__(512, 1)
void attn_tc(const float* __restrict__ mask, float* __restrict__ out)
{
    extern __shared__ char smc[];
    const uint32_t sbu = smem_u32(smc);
    __half* S23 = (__half*)(smc + SM_S23);    // [128][SSTR]
    __half* Qh = (__half*)(smc + SM_QH);
    __half* Ph = (__half*)(smc + SM_PH);
    float* Pm = (float*)(smc + SM_PM);        // [64][2] partial max
    float* Ps = (float*)(smc + SM_PS);        // [64][2] partial sum
    float* MrB = (float*)(smc + SM_MR);       // [2][64]
    float* LsB = (float*)(smc + SM_LS);       // [2][64]
    float* Cs = (float*)(smc + SM_CS);

    const int t = threadIdx.x, lane = t & 31, w = t >> 5;   // 16 warps
    const int g = lane >> 2, t4 = lane & 3;
    const int l0 = blockIdx.x * 64, hd = blockIdx.y, b = blockIdx.z;

    // GEMM2/gather mapping (warps 8-15): 4m x 2n grid of 16x32 tiles
    const int w8   = w - 8;
    const int sm0g = (w8 & 3) * 16;
    const int sn0g = (w8 >> 2) * 32;
    const int half = w8 >> 2;

    const __half* Qg = g_Q + ((size_t)(b * NH + hd) * LQ + l0) * DHD;
    const __half* Kg = g_K + (size_t)(b * NH + hd) * LK * DHD;
    const __half* Vg = g_Vt + (size_t)(b * NH + hd) * DHD * LK;
    const float* mg = mask + (size_t)b * LK;

    // initial loads: Q + first buffer
    {
        const int row = t >> 3, c = t & 7;
        cp_async16(sbu + SM_QH + row * 144 + c * 16, Qg + row * DHD + c * 8);
        cp_async16(sbu + SM_BUF + OFF_KH + row * 144 + c * 16, Kg + (size_t)row * DHD + c * 8);
        cp_async16(sbu + SM_BUF + OFF_VTH + row * 144 + c * 16, Vg + (size_t)row * LK + c * 8);
        const int eb0 = l0 + (MAXPOS - 64);
#pragma unroll
        for (int i = 0; i < 2; i++) {
            int q = t + 512 * i;
            if (q < 127 * 8) {
                int rw = q >> 3, cc = q & 7;
                cp_async16(sbu + SM_BUF + OFF_ES + rw * 144 + cc * 16,
                           g_E + (size_t)(eb0 + rw) * DHD + cc * 8);
            }
        }
        if (t < 16) cp_async16(sbu + SM_BUF + OFF_MS + t * 16, mg + t * 4);
        cp_commit();
    }

    if (t < 64) { MrB[t] = -1e30f; LsB[t] = 0.f; }
    if (t < 72) {
        int bb = t / 36, wd = t % 36;
        *(uint32_t*)(smc + SM_BUF + bb * BUF_BYTES + OFF_ES + 127 * 144 + wd * 4) = 0u;
    }

    // PV accumulators (warps 0-3): 16x64 tile each
    float O[8][4];
#pragma unroll
    for (int j = 0; j < 8; j++)
#pragma unroll
        for (int q = 0; q < 4; q++) O[j][q] = 0.f;

    // GEMM1 per-warp (warps 0-7)
    const bool isQ = (w < 4);
    const int rk    = isQ ? 0 : (w - 4) * 16;
    const int arow0 = isQ ? w * 16 : rk;
    const int band0 = isQ ? w * 16 : 48 - rk;
    const int drow0 = isQ ? w * 16 : 64 + rk;

    for (int kt = 0; kt < LK / 64; kt++) {
        const int bb = kt & 1;
        const char* B = smc + SM_BUF + bb * BUF_BYTES;
        const float* MrC = MrB + (kt & 1) * 64;
        float* MrN = MrB + ((kt & 1) ^ 1) * 64;
        const float* LsC = LsB + (kt & 1) * 64;
        float* LsN = LsB + ((kt & 1) ^ 1) * 64;

        cp_wait<0>();
        __syncthreads();   // B1: tiles ready; prior PV/gather done

        if (kt + 1 < LK / 64) {
            const int r1 = (kt + 1) * 64;
            const uint32_t P = sbu + SM_BUF + (bb ^ 1) * BUF_BYTES;
            const int row = t >> 3, c = t & 7;
            cp_async16(P + OFF_KH + row * 144 + c * 16, Kg + (size_t)(r1 + row) * DHD + c * 8);
            cp_async16(P + OFF_VTH + row * 144 + c * 16, Vg + (size_t)row * LK + r1 + c * 8);
            const int eb1 = l0 - r1 + (MAXPOS - 64);
#pragma unroll
            for (int i = 0; i < 2; i++) {
                int q = t + 512 * i;
                if (q < 127 * 8) {
                    int rw = q >> 3, cc = q & 7;
                    cp_async16(P + OFF_ES + rw * 144 + cc * 16,
                               g_E + (size_t)(eb1 + rw) * DHD + cc * 8);
                }
            }
            if (t < 16) cp_async16(P + OFF_MS + t * 16, mg + r1 + t * 4);
            cp_commit();
        }

        const __half* KhS = (const __half*)(B + OFF_KH);
        const __half* VhS = (const __half*)(B + OFF_VTH);
        const __half* EsS = (const __half*)(B + OFF_ES);
        const float* MsS = (const float*)(B + OFF_MS);

        float sc[4][4];   // GEMM2 accumulators / logits (warps 8-15)

        if (w < 8) {
            // ---- GEMM1 (banded, A-frags hoisted) ----
            const __half* Ab = isQ ? Qh : KhS;
            uint32_t aAll[4][4];
#pragma unroll
            for (int k4 = 0; k4 < 4; k4++) {
                const int kk = k4 * 16 + t4 * 2;
                const int r = arow0 + g;
                aAll[k4][0] = *(const uint32_t*)&Ab[r * STR + kk];
                aAll[k4][1] = *(const uint32_t*)&Ab[(r + 8) * STR + kk];
                aAll[k4][2] = *(const uint32_t*)&Ab[r * STR + kk + 8];
                aAll[k4][3] = *(const uint32_t*)&Ab[(r + 8) * STR + kk + 8];
            }
#pragma unroll
            for (int hf = 0; hf < 2; hf++) {
                const int nt0 = band0 / 8 + hf * 5;
                float ea[5][4];
#pragma unroll
                for (int j = 0; j < 5; j++)
#pragma unroll
                    for (int q = 0; q < 4; q++) ea[j][q] = 0.f;
#pragma unroll
                for (int k4 = 0; k4 < 4; k4++) {
                    const int kk = k4 * 16 + t4 * 2;
#pragma unroll
                    for (int j = 0; j < 5; j++) {
                        const int n = (nt0 + j) * 8 + g;
                        uint32_t bf2[2];
                        bf2[0] = *(const uint32_t*)&EsS[n * STR + kk];
                        bf2[1] = *(const uint32_t*)&EsS[n * STR + kk + 8];
                        mma_f16(ea[j], aAll[k4], bf2);
                    }
                }
#pragma unroll
                for (int j = 0; j < 5; j++) {
                    const int m = drow0 + g, n = (nt0 + j) * 8 + t4 * 2;
                    *(uint32_t*)&S23[m * SSTR + n] = hpack(ea[j][0], ea[j][1]);
                    *(uint32_t*)&S23[(m + 8) * SSTR + n] = hpack(ea[j][2], ea[j][3]);
                }
            }
        } else {
            // ---- GEMM2: Q@K^T, 16x32 warp tiles ----
#pragma unroll
            for (int j = 0; j < 4; j++)
#pragma unroll
                for (int q = 0; q < 4; q++) sc[j][q] = 0.f;
#pragma unroll
            for (int k4 = 0; k4 < 4; k4++) {
                const int kk = k4 * 16 + t4 * 2;
                uint32_t aF[4];
                const int r = sm0g + g;
                aF[0] = *(const uint32_t*)&Qh[r * STR + kk];
                aF[1] = *(const uint32_t*)&Qh[(r + 8) * STR + kk];
                aF[2] = *(const uint32_t*)&Qh[r * STR + kk + 8];
                aF[3] = *(const uint32_t*)&Qh[(r + 8) * STR + kk + 8];
#pragma unroll
                for (int j = 0; j < 4; j++) {
                    const int n = sn0g + j * 8 + g;
                    uint32_t bF[2];
                    bF[0] = *(const uint32_t*)&KhS[n * STR + kk];
                    bF[1] = *(const uint32_t*)&KhS[n * STR + kk + 8];
                    mma_f16(sc[j], aF, bF);
                }
            }
        }
        __syncthreads();   // B2: S23 visible

        // ---- gather + partial softmax (warps 8-15), logits in registers ----
        float mw[2], sw[2];
        if (w >= 8) {
#pragma unroll
            for (int ch = 0; ch < 2; ch++) mw[ch] = -1e30f;
#pragma unroll
            for (int j = 0; j < 4; j++) {
                const int ri = sn0g + j * 8 + t4 * 2;
#pragma unroll
                for (int ch = 0; ch < 2; ch++) {
                    const int li = sm0g + g + ch * 8;
                    const int nn = li - ri + 63;
                    float t0 = __half2float(S23[li * SSTR + nn])
                             + __half2float(S23[(64 + ri) * SSTR + nn]);
                    float t1 = __half2float(S23[li * SSTR + nn - 1])
                             + __half2float(S23[(65 + ri) * SSTR + nn - 1]);
                    float v0 = (sc[j][ch * 2 + 0] + t0) * 0.125f + MsS[ri];
                    float v1 = (sc[j][ch * 2 + 1] + t1) * 0.125f + MsS[ri + 1];
                    sc[j][ch * 2 + 0] = v0;
                    sc[j][ch * 2 + 1] = v1;
                    mw[ch] = fmaxf(mw[ch], fmaxf(v0, v1));
                }
            }
#pragma unroll
            for (int ch = 0; ch < 2; ch++) {
                mw[ch] = fmaxf(mw[ch], __shfl_xor_sync(0xffffffffu, mw[ch], 1));
                mw[ch] = fmaxf(mw[ch], __shfl_xor_sync(0xffffffffu, mw[ch], 2));
                float s = 0.f;
#pragma unroll
                for (int j = 0; j < 4; j++) {
                    float e0 = __expf(sc[j][ch * 2 + 0] - mw[ch]);
                    float e1 = __expf(sc[j][ch * 2 + 1] - mw[ch]);
                    sc[j][ch * 2 + 0] = e0;
                    sc[j][ch * 2 + 1] = e1;
                    s += e0 + e1;
                }
                s += __shfl_xor_sync(0xffffffffu, s, 1);
                s += __shfl_xor_sync(0xffffffffu, s, 2);
                sw[ch] = s;
                if (t4 == 0) {
                    const int row = sm0g + g + ch * 8;
                    Pm[row * 2 + half] = mw[ch];
                    Ps[row * 2 + half] = s;
                }
            }
        }
        __syncthreads();   // B3: partials visible

        // ---- finalize (warps 8-15): rescale, store P; update state ----
        if (w >= 8) {
#pragma unroll
            for (int ch = 0; ch < 2; ch++) {
                const int row = sm0g + g + ch * 8;
                const float ma = Pm[row * 2], mb2 = Pm[row * 2 + 1];
                const float mold = MrC[row];
                const float mnew = fmaxf(fmaxf(ma, mb2), mold);
                const float f = __expf(mw[ch] - mnew);
#pragma unroll
                for (int j = 0; j < 4; j++) {
                    *(uint32_t*)&Ph[row * STR + sn0g + j * 8 + t4 * 2] =
                        hpack(sc[j][ch * 2 + 0] * f, sc[j][ch * 2 + 1] * f);
                }
                if (half == 0 && t4 == 0) {
                    const float corr = __expf(mold - mnew);
                    const float st = Ps[row * 2] * __expf(ma - mnew)
                                   + Ps[row * 2 + 1] * __expf(mb2 - mnew);
                    LsN[row] = LsC[row] * corr + st;
                    MrN[row] = mnew;
                    Cs[row] = corr;
                }
            }
        }
        __syncthreads();   // B4: Ph, Cs visible

        // ---- PV (warps 0-3, 16x64 tiles) ----
        if (w < 4) {
            const int pm0 = w * 16;
            const float c0 = Cs[pm0 + g];
            const float c1 = Cs[pm0 + g + 8];
#pragma unroll
            for (int j = 0; j < 8; j++) {
                O[j][0] *= c0; O[j][1] *= c0;
                O[j][2] *= c1; O[j][3] *= c1;
            }
#pragma unroll
            for (int k4 = 0; k4 < 4; k4++) {
                const int kk = k4 * 16 + t4 * 2;
                uint32_t aF[4];
                const int r = pm0 + g;
                aF[0] = *(const uint32_t*)&Ph[r * STR + kk];
                aF[1] = *(const uint32_t*)&Ph[(r + 8) * STR + kk];
                aF[2] = *(const uint32_t*)&Ph[r * STR + kk + 8];
                aF[3] = *(const uint32_t*)&Ph[(r + 8) * STR + kk + 8];
#pragma unroll
                for (int j = 0; j < 8; j++) {
                    const int d = j * 8 + g;
                    uint32_t bF[2];
                    bF[0] = *(const uint32_t*)&VhS[d * STR + kk];
                    bF[1] = *(const uint32_t*)&VhS[d * STR + kk + 8];
                    mma_f16(O[j], aF, bF);
                }
            }
        }
    }

    // ---- output [B, Lq, H*64] (warps 0-3; final Ls in buffer 0 after even #ktiles) ----
    if (w < 4) {
        const float* LsF = LsB;   // buffer 0
#pragma unroll
        for (int ch = 0; ch < 2; ch++) {
            const int li = w * 16 + g + ch * 8;
            const float inv = 1.0f / LsF[li];
            float* op = out + ((size_t)(b * LQ) + l0 + li) * DM + hd * 64;
#pragma unroll
            for (int j = 0; j < 8; j++) {
                float2 o;
                o.x = O[j][ch * 2 + 0] * inv;
                o.y = O[j][ch * 2 + 1] * inv;
                *(float2*)(op + j * 8 + t4 * 2) = o;
            }
        }
    }
}

// =================================================================================
extern "C" void kernel_launch(void* const* d_in, const int* in_sizes, int n_in,
                              void* d_out, int out_size)
{
    const float* hidden   = (const float*)d_in[0];
    const float* q_hidden = (const float*)d_in[1];
    const float* mask     = (const float*)d_in[2];
    const float* Wq       = (const float*)d_in[3];
    const float* bq       = (const float*)d_in[4];
    const float* Wk       = (const float*)d_in[5];
    const float* bk       = (const float*)d_in[6];
    const float* Wv       = (const float*)d_in[7];
    const float* bv       = (const float*)d_in[8];
    const float* dist     = (const float*)d_in[9];
    float* out = (float*)d_out;

    __half *Qp, *Kp, *Vtp, *Ep, *Xq, *Xk, *Wp;
    cudaGetSymbolAddress((void**)&Qp,  g_Q);
    cudaGetSymbolAddress((void**)&Kp,  g_K);
    cudaGetSymbolAddress((void**)&Vtp, g_Vt);
    cudaGetSymbolAddress((void**)&Ep,  g_E);
    cudaGetSymbolAddress((void**)&Xq,  g_Xq);
    cudaGetSymbolAddress((void**)&Xk,  g_Xk);
    cudaGetSymbolAddress((void**)&Wp,  g_W);

    cudaFuncSetAttribute(proj_tc, cudaFuncAttributeMaxDynamicSharedMemorySize,
                         PROJ_SMEM_BYTES);
    cudaFuncSetAttribute(attn_tc, cudaFuncAttributeMaxDynamicSharedMemorySize,
                         ATTN_SMEM);

    const int nq = NB * LQ * DM / 4;
    const int nk = NB * LK * DM / 4;
    const int nw = DM * DM / 4;
    const int ne = (2 * MAXPOS - 1) * DHD / 4;
    convh_kernel<<<(nq + 255) / 256, 256>>>(q_hidden, Xq, nq);
    convh_kernel<<<(nk + 255) / 256, 256>>>(hidden,   Xk, nk);
    convh_kernel<<<(nw + 255) / 256, 256>>>(Wq, Wp + 0 * (size_t)DM * DM, nw);
    convh_kernel<<<(nw + 255) / 256, 256>>>(Wk, Wp + 1 * (size_t)DM * DM, nw);
    convh_kernel<<<(nw + 255) / 256, 256>>>(Wv, Wp + 2 * (size_t)DM * DM, nw);
    convh_kernel<<<(ne + 255) / 256, 256>>>(dist, Ep, ne);

    dim3 gq(NB * LQ / 128, DM / 128);
    dim3 gk(NB * LK / 128, DM / 128);
    proj_tc<<<gq, 256, PROJ_SMEM_BYTES>>>(Xq, Wp + 0 * (size_t)DM * DM, bq, Qp,  LQ, 0);
    proj_tc<<<gk, 256, PROJ_SMEM_BYTES>>>(Xk, Wp + 1 * (size_t)DM * DM, bk, Kp,  LK, 0);
    proj_tc<<<gk, 256, PROJ_SMEM_BYTES>>>(Xk, Wp + 2 * (size_t)DM * DM, bv, Vtp, LK, 1);

    dim3 ga(LQ / 64, NH, NB);
    attn_tc<<<ga, 512, ATTN_SMEM>>>(mask, out);
}

// round 15
// speedup vs baseline: 1.2317x; 1.1505x over previous
#include <cuda_runtime.h>
#include <cuda_fp16.h>
#include <math.h>
#include <stdint.h>
#include <string.h>

#define NH   16
#define DHD  64
#define NB   4
#define LQ   1024
#define LK   2048
#define DM   1024
#define MAXPOS 2048
#define STR  72    // fp16 smem row stride (144B)
#define SSTR 136   // S23 fp16 stride

// ---------------- static device scratch ----------------
__device__ __half g_Q[(size_t)NB*NH*LQ*DHD];
__device__ __half g_K[(size_t)NB*NH*LK*DHD];
__device__ __half g_Vt[(size_t)NB*NH*DHD*LK];   // [b,h][d][r]
__device__ __half g_E[(size_t)(2*MAXPOS-1)*DHD];

__device__ __half g_Xq[(size_t)NB*LQ*DM];
__device__ __half g_Xk[(size_t)NB*LK*DM];
__device__ __half g_W[3][(size_t)DM*DM];

// ============================ helpers ============================
__device__ __forceinline__ uint32_t smem_u32(const void* p) {
    uint32_t a;
    asm("{ .reg .u64 t; cvta.to.shared.u64 t, %1; cvt.u32.u64 %0, t; }"
        : "=r"(a) : "l"(p));
    return a;
}
__device__ __forceinline__ void cp_async16(uint32_t saddr, const void* gaddr) {
    asm volatile("cp.async.cg.shared.global [%0], [%1], 16;" :: "r"(saddr), "l"(gaddr));
}
__device__ __forceinline__ void cp_commit() { asm volatile("cp.async.commit_group;"); }
template <int N>
__device__ __forceinline__ void cp_wait() { asm volatile("cp.async.wait_group %0;" :: "n"(N)); }

__device__ __forceinline__ void mma_f16(float* c, const uint32_t* a, const uint32_t* b) {
    asm volatile(
        "mma.sync.aligned.m16n8k16.row.col.f32.f16.f16.f32 "
        "{%0,%1,%2,%3}, {%4,%5,%6,%7}, {%8,%9}, {%0,%1,%2,%3};"
        : "+f"(c[0]), "+f"(c[1]), "+f"(c[2]), "+f"(c[3])
        : "r"(a[0]), "r"(a[1]), "r"(a[2]), "r"(a[3]), "r"(b[0]), "r"(b[1]));
}
__device__ __forceinline__ uint32_t hpack(float x, float y) {
    __half2 h = __floats2half2_rn(x, y);
    uint32_t u; memcpy(&u, &h, 4); return u;
}

// =================================================================================
// Fused fp32->fp16 conversion for all 6 tensors (one launch)
// =================================================================================
__global__ void convall_kernel(
    const float* __restrict__ s0, __half* __restrict__ d0, int n0,
    const float* __restrict__ s1, __half* __restrict__ d1, int n1,
    const float* __restrict__ s2, __half* __restrict__ d2, int n2,
    const float* __restrict__ s3, __half* __restrict__ d3, int n3,
    const float* __restrict__ s4, __half* __restrict__ d4, int n4,
    const float* __restrict__ s5, __half* __restrict__ d5, int n5)
{
    int i = blockIdx.x * blockDim.x + threadIdx.x;
    const float* s; __half* d; int k = i;
    if      (k < n0)                         { s = s0; d = d0; }
    else if ((k -= n0) < n1)                 { s = s1; d = d1; }
    else if ((k -= n1) < n2)                 { s = s2; d = d2; }
    else if ((k -= n2) < n3)                 { s = s3; d = d3; }
    else if ((k -= n3) < n4)                 { s = s4; d = d4; }
    else if ((k -= n4) < n5)                 { s = s5; d = d5; }
    else return;
    float4 v = ((const float4*)s)[k];
    ((uint32_t*)d)[2*k]   = hpack(v.x, v.y);
    ((uint32_t*)d)[2*k+1] = hpack(v.z, v.w);
}

// =================================================================================
// Projection GEMM, fp16 single-pass (proven R9)
// =================================================================================
#define BK      32
#define KS_STR  40
#define TILE_HF (128 * KS_STR)
#define STAGE_HF (2 * TILE_HF)
#define PROJ_SMEM_BYTES (2 * STAGE_HF * 2)

__global__ __launch_bounds__(256)
void proj_tc(const __half* __restrict__ A_g, const __half* __restrict__ B_g,
             const float* __restrict__ bias,
             __half* __restrict__ outH, int L, int mode)
{
    extern __shared__ __half smem[];
    const uint32_t smem_b = smem_u32(smem);
    const int t = threadIdx.x, lane = t & 31;
    const int wid = t >> 5, g = lane >> 2, t4 = lane & 3;
    const int wm0 = (wid & 3) * 32, wn0 = (wid >> 2) * 64;
    const int m0 = blockIdx.x * 128, n0 = blockIdx.y * 128;
    const int c0 = t * 2;
    const int row0 = c0 >> 2, seg0 = c0 & 3;
    const int row1 = (c0 + 1) >> 2, seg1 = (c0 + 1) & 3;
    const int NS = DM / BK;

    auto load_stage = [&](int kc) {
        const int k0 = kc * BK;
        const uint32_t sb = smem_b + (uint32_t)(kc & 1) * STAGE_HF * 2;
        const uint32_t so0 = (uint32_t)(row0 * KS_STR + seg0 * 8) * 2;
        const uint32_t so1 = (uint32_t)(row1 * KS_STR + seg1 * 8) * 2;
        cp_async16(sb + so0, A_g + (size_t)(m0 + row0) * DM + k0 + seg0 * 8);
        cp_async16(sb + so1, A_g + (size_t)(m0 + row1) * DM + k0 + seg1 * 8);
        cp_async16(sb + TILE_HF * 2 + so0, B_g + (size_t)(n0 + row0) * DM + k0 + seg0 * 8);
        cp_async16(sb + TILE_HF * 2 + so1, B_g + (size_t)(n0 + row1) * DM + k0 + seg1 * 8);
        cp_commit();
    };

    float acc[2][8][4];
#pragma unroll
    for (int i = 0; i < 2; i++)
#pragma unroll
        for (int j = 0; j < 8; j++)
#pragma unroll
            for (int q = 0; q < 4; q++) acc[i][j][q] = 0.0f;

    load_stage(0);
    for (int kc = 0; kc < NS; kc++) {
        if (kc + 1 < NS) { load_stage(kc + 1); cp_wait<1>(); }
        else             { cp_wait<0>(); }
        __syncthreads();
        const __half* sA = smem + (size_t)(kc & 1) * STAGE_HF;
        const __half* sB = sA + TILE_HF;
#pragma unroll
        for (int ks = 0; ks < BK; ks += 16) {
            uint32_t aF[2][4], bF[8][2];
            const int kk = ks + t4 * 2;
#pragma unroll
            for (int i = 0; i < 2; i++) {
                const int r = wm0 + i * 16 + g;
                aF[i][0] = *(const uint32_t*)&sA[r * KS_STR + kk];
                aF[i][1] = *(const uint32_t*)&sA[(r + 8) * KS_STR + kk];
                aF[i][2] = *(const uint32_t*)&sA[r * KS_STR + kk + 8];
                aF[i][3] = *(const uint32_t*)&sA[(r + 8) * KS_STR + kk + 8];
            }
#pragma unroll
            for (int j = 0; j < 8; j++) {
                const int n = wn0 + j * 8 + g;
                bF[j][0] = *(const uint32_t*)&sB[n * KS_STR + kk];
                bF[j][1] = *(const uint32_t*)&sB[n * KS_STR + kk + 8];
            }
#pragma unroll
            for (int i = 0; i < 2; i++)
#pragma unroll
                for (int j = 0; j < 8; j++)
                    mma_f16(acc[i][j], aF[i], bF[j]);
        }
        __syncthreads();
    }
#pragma unroll
    for (int i = 0; i < 2; i++)
#pragma unroll
        for (int j = 0; j < 8; j++) {
            const int cc = n0 + wn0 + j * 8 + t4 * 2;
            const int hh = cc >> 6, dh = cc & 63;
            const float b0 = __ldg(&bias[cc]), b1 = __ldg(&bias[cc + 1]);
#pragma unroll
            for (int rr = 0; rr < 2; rr++) {
                const int r = m0 + wm0 + i * 16 + g + rr * 8;
                const int bidx = r / L, l = r - bidx * L;
                const float f0 = acc[i][j][rr * 2 + 0] + b0;
                const float f1 = acc[i][j][rr * 2 + 1] + b1;
                if (mode == 0) {
                    const size_t base = ((size_t)(bidx * NH + hh) * L + l) * DHD + dh;
                    *(__half2*)&outH[base] = __floats2half2_rn(f0, f1);
                } else {
                    const size_t base = ((size_t)(bidx * NH + hh) * DHD + dh) * LK + l;
                    outH[base] = __float2half(f0);
                    outH[base + LK] = __float2half(f1);
                }
            }
        }
}

// =================================================================================
// Tensor-core attention: 256 threads, 111KB smem -> 2 CTAs/SM, E single-buffered
// =================================================================================
#define SM_S23 0
#define SM_QH  34816
#define SM_K0  44032
#define SM_K1  53248
#define SM_V0  62464
#define SM_V1  71680
#define SM_ES  80896
#define SM_MS0 99328
#define SM_MS1 99584
#define SM_PH  99840
#define SM_PM  109056
#define SM_PS  109568
#define SM_MR  110080   // double-buffered [2][64]
#define SM_LS  110592   // double-buffered [2][64]
#define SM_CS  111104
#define ATTN_SMEM 111360

__global__ __launch_bounds__(256, 2)
void attn_tc(const float* __restrict__ mask, float* __restrict__ out)
{
    extern __shared__ char smc[];
    const uint32_t sbu = smem_u32(smc);
    __half* S23 = (__half*)(smc + SM_S23);    // [128][SSTR]
    __half* Qh = (__half*)(smc + SM_QH);
    __half* Ph = (__half*)(smc + SM_PH);
    float* Pm = (float*)(smc + SM_PM);        // [64][2]
    float* Ps = (float*)(smc + SM_PS);        // [64][2]
    float* MrB = (float*)(smc + SM_MR);       // [2][64]
    float* LsB = (float*)(smc + SM_LS);       // [2][64]
    float* Cs = (float*)(smc + SM_CS);

    const int t = threadIdx.x, lane = t & 31, w = t >> 5;   // 8 warps
    const int g = lane >> 2, t4 = lane & 3;
    const int l0 = blockIdx.x * 64, hd = blockIdx.y, b = blockIdx.z;

    // GEMM2 / gather / PV mapping: 4m x 2n grid of 16x32 tiles
    const int sm0g = (w & 3) * 16;
    const int sn0g = (w >> 2) * 32;
    const int half = w >> 2;

    const __half* Qg = g_Q + ((size_t)(b * NH + hd) * LQ + l0) * DHD;
    const __half* Kg = g_K + (size_t)(b * NH + hd) * LK * DHD;
    const __half* Vg = g_Vt + (size_t)(b * NH + hd) * DHD * LK;
    const float* mg = mask + (size_t)b * LK;

    // initial loads: Q + K0 + V0 + E + mask0  (64 rows x 8 chunks = 512)
    for (int c = t; c < 512; c += 256) {
        const int row = c >> 3, cc = c & 7;
        cp_async16(sbu + SM_QH + row * 144 + cc * 16, Qg + row * DHD + cc * 8);
        cp_async16(sbu + SM_K0 + row * 144 + cc * 16, Kg + (size_t)row * DHD + cc * 8);
        cp_async16(sbu + SM_V0 + row * 144 + cc * 16, Vg + (size_t)row * LK + cc * 8);
    }
    {
        const int eb0 = l0 + (MAXPOS - 64);
        for (int c = t; c < 127 * 8; c += 256) {
            const int rw = c >> 3, cc = c & 7;
            cp_async16(sbu + SM_ES + rw * 144 + cc * 16,
                       g_E + (size_t)(eb0 + rw) * DHD + cc * 8);
        }
        if (t < 16) cp_async16(sbu + SM_MS0 + t * 16, mg + t * 4);
        cp_commit();
    }

    if (t < 64) { MrB[t] = -1e30f; LsB[t] = 0.f; }
    if (t < 36) *(uint32_t*)(smc + SM_ES + 127 * 144 + t * 4) = 0u;  // E row 127 = 0

    float O[4][4];
#pragma unroll
    for (int j = 0; j < 4; j++)
#pragma unroll
        for (int q = 0; q < 4; q++) O[j][q] = 0.f;

    // GEMM1 per-warp: full 16-row m-block, 10 n-tile band in 2 passes
    const bool isQ = (w < 4);
    const int rk    = isQ ? 0 : (w - 4) * 16;
    const int arow0 = isQ ? w * 16 : rk;
    const int band0 = isQ ? w * 16 : 48 - rk;
    const int drow0 = isQ ? w * 16 : 64 + rk;

    const int NT = LK / 64;
    for (int kt = 0; kt < NT; kt++) {
        const int par = kt & 1;
        const char* Kb = smc + (par ? SM_K1 : SM_K0);
        const char* Vb = smc + (par ? SM_V1 : SM_V0);
        const float* MsS = (const float*)(smc + (par ? SM_MS1 : SM_MS0));
        const float* MrC = MrB + par * 64;
        float* MrN = MrB + (par ^ 1) * 64;
        const float* LsC = LsB + par * 64;
        float* LsN = LsB + (par ^ 1) * 64;

        cp_wait<0>();
        __syncthreads();   // B1: K/V/E/mask ready; prior phases done

        if (kt + 1 < NT) {  // prefetch K/V/mask for kt+1 (E after B2)
            const int r1 = (kt + 1) * 64;
            const uint32_t Kp2 = sbu + (par ? SM_K0 : SM_K1);
            const uint32_t Vp2 = sbu + (par ? SM_V0 : SM_V1);
            for (int c = t; c < 512; c += 256) {
                const int row = c >> 3, cc = c & 7;
                cp_async16(Kp2 + row * 144 + cc * 16, Kg + (size_t)(r1 + row) * DHD + cc * 8);
                cp_async16(Vp2 + row * 144 + cc * 16, Vg + (size_t)row * LK + r1 + cc * 8);
            }
            if (t < 16) cp_async16(sbu + (par ? SM_MS0 : SM_MS1) + t * 16, mg + r1 + t * 4);
            cp_commit();
        }

        const __half* KhS = (const __half*)Kb;
        const __half* VhS = (const __half*)Vb;
        const __half* EsS = (const __half*)(smc + SM_ES);

        // ---- GEMM1 (banded, A-frags hoisted) ----
        {
            const __half* Ab = isQ ? Qh : KhS;
            uint32_t aAll[4][4];
#pragma unroll
            for (int k4 = 0; k4 < 4; k4++) {
                const int kk = k4 * 16 + t4 * 2;
                const int r = arow0 + g;
                aAll[k4][0] = *(const uint32_t*)&Ab[r * STR + kk];
                aAll[k4][1] = *(const uint32_t*)&Ab[(r + 8) * STR + kk];
                aAll[k4][2] = *(const uint32_t*)&Ab[r * STR + kk + 8];
                aAll[k4][3] = *(const uint32_t*)&Ab[(r + 8) * STR + kk + 8];
            }
#pragma unroll
            for (int hf = 0; hf < 2; hf++) {
                const int nt0 = band0 / 8 + hf * 5;
                float ea[5][4];
#pragma unroll
                for (int j = 0; j < 5; j++)
#pragma unroll
                    for (int q = 0; q < 4; q++) ea[j][q] = 0.f;
#pragma unroll
                for (int k4 = 0; k4 < 4; k4++) {
                    const int kk = k4 * 16 + t4 * 2;
#pragma unroll
                    for (int j = 0; j < 5; j++) {
                        const int n = (nt0 + j) * 8 + g;
                        uint32_t bf2[2];
                        bf2[0] = *(const uint32_t*)&EsS[n * STR + kk];
                        bf2[1] = *(const uint32_t*)&EsS[n * STR + kk + 8];
                        mma_f16(ea[j], aAll[k4], bf2);
                    }
                }
#pragma unroll
                for (int j = 0; j < 5; j++) {
                    const int m = drow0 + g, n = (nt0 + j) * 8 + t4 * 2;
                    *(uint32_t*)&S23[m * SSTR + n] = hpack(ea[j][0], ea[j][1]);
                    *(uint32_t*)&S23[(m + 8) * SSTR + n] = hpack(ea[j][2], ea[j][3]);
                }
            }
        }
        // ---- GEMM2: Q@K^T, 16x32 warp tiles ----
        float sc[4][4];
#pragma unroll
        for (int j = 0; j < 4; j++)
#pragma unroll
            for (int q = 0; q < 4; q++) sc[j][q] = 0.f;
#pragma unroll
        for (int k4 = 0; k4 < 4; k4++) {
            const int kk = k4 * 16 + t4 * 2;
            uint32_t aF[4];
            const int r = sm0g + g;
            aF[0] = *(const uint32_t*)&Qh[r * STR + kk];
            aF[1] = *(const uint32_t*)&Qh[(r + 8) * STR + kk];
            aF[2] = *(const uint32_t*)&Qh[r * STR + kk + 8];
            aF[3] = *(const uint32_t*)&Qh[(r + 8) * STR + kk + 8];
#pragma unroll
            for (int j = 0; j < 4; j++) {
                const int n = sn0g + j * 8 + g;
                uint32_t bF[2];
                bF[0] = *(const uint32_t*)&KhS[n * STR + kk];
                bF[1] = *(const uint32_t*)&KhS[n * STR + kk + 8];
                mma_f16(sc[j], aF, bF);
            }
        }
        __syncthreads();   // B2: S23 visible; E reads done

        if (kt + 1 < NT) {  // E prefetch (single buffer, GEMM1 finished reading)
            const int eb1 = l0 - (kt + 1) * 64 + (MAXPOS - 64);
            for (int c = t; c < 127 * 8; c += 256) {
                const int rw = c >> 3, cc = c & 7;
                cp_async16(sbu + SM_ES + rw * 144 + cc * 16,
                           g_E + (size_t)(eb1 + rw) * DHD + cc * 8);
            }
            cp_commit();
        }

        // ---- gather + partial softmax (logits in registers) ----
        float mw[2];
#pragma unroll
        for (int ch = 0; ch < 2; ch++) mw[ch] = -1e30f;
#pragma unroll
        for (int j = 0; j < 4; j++) {
            const int ri = sn0g + j * 8 + t4 * 2;
#pragma unroll
            for (int ch = 0; ch < 2; ch++) {
                const int li = sm0g + g + ch * 8;
                const int nn = li - ri + 63;
                float t0 = __half2float(S23[li * SSTR + nn])
                         + __half2float(S23[(64 + ri) * SSTR + nn]);
                float t1 = __half2float(S23[li * SSTR + nn - 1])
                         + __half2float(S23[(65 + ri) * SSTR + nn - 1]);
                float v0 = (sc[j][ch * 2 + 0] + t0) * 0.125f + MsS[ri];
                float v1 = (sc[j][ch * 2 + 1] + t1) * 0.125f + MsS[ri + 1];
                sc[j][ch * 2 + 0] = v0;
                sc[j][ch * 2 + 1] = v1;
                mw[ch] = fmaxf(mw[ch], fmaxf(v0, v1));
            }
        }
#pragma unroll
        for (int ch = 0; ch < 2; ch++) {
            mw[ch] = fmaxf(mw[ch], __shfl_xor_sync(0xffffffffu, mw[ch], 1));
            mw[ch] = fmaxf(mw[ch], __shfl_xor_sync(0xffffffffu, mw[ch], 2));
            float s = 0.f;
#pragma unroll
            for (int j = 0; j < 4; j++) {
                float e0 = __expf(sc[j][ch * 2 + 0] - mw[ch]);
                float e1 = __expf(sc[j][ch * 2 + 1] - mw[ch]);
                sc[j][ch * 2 + 0] = e0;
                sc[j][ch * 2 + 1] = e1;
                s += e0 + e1;
            }
            s += __shfl_xor_sync(0xffffffffu, s, 1);
            s += __shfl_xor_sync(0xffffffffu, s, 2);
            if (t4 == 0) {
                const int row = sm0g + g + ch * 8;
                Pm[row * 2 + half] = mw[ch];
                Ps[row * 2 + half] = s;
            }
        }
        __syncthreads();   // B3: partials visible

        // ---- finalize: rescale, store P; update state ----
#pragma unroll
        for (int ch = 0; ch < 2; ch++) {
            const int row = sm0g + g + ch * 8;
            const float ma = Pm[row * 2], mb2 = Pm[row * 2 + 1];
            const float mold = MrC[row];
            const float mnew = fmaxf(fmaxf(ma, mb2), mold);
            const float f = __expf(mw[ch] - mnew);
#pragma unroll
            for (int j = 0; j < 4; j++) {
                *(uint32_t*)&Ph[row * STR + sn0g + j * 8 + t4 * 2] =
                    hpack(sc[j][ch * 2 + 0] * f, sc[j][ch * 2 + 1] * f);
            }
            if (half == 0 && t4 == 0) {
                const float corr = __expf(mold - mnew);
                const float st = Ps[row * 2] * __expf(ma - mnew)
                               + Ps[row * 2 + 1] * __expf(mb2 - mnew);
                LsN[row] = LsC[row] * corr + st;
                MrN[row] = mnew;
                Cs[row] = corr;
            }
        }
        __syncthreads();   // B4: Ph, Cs visible

        // ---- PV (all 8 warps, 16x32 tiles) ----
        {
            const float c0 = Cs[sm0g + g];
            const float c1 = Cs[sm0g + g + 8];
#pragma unroll
            for (int j = 0; j < 4; j++) {
                O[j][0] *= c0; O[j][1] *= c0;
                O[j][2] *= c1; O[j][3] *= c1;
            }
        }
#pragma unroll
        for (int k4 = 0; k4 < 4; k4++) {
            const int kk = k4 * 16 + t4 * 2;
            uint32_t aF[4];
            const int r = sm0g + g;
            aF[0] = *(const uint32_t*)&Ph[r * STR + kk];
            aF[1] = *(const uint32_t*)&Ph[(r + 8) * STR + kk];
            aF[2] = *(const uint32_t*)&Ph[r * STR + kk + 8];
            aF[3] = *(const uint32_t*)&Ph[(r + 8) * STR + kk + 8];
#pragma unroll
            for (int j = 0; j < 4; j++) {
                const int d = sn0g + j * 8 + g;
                uint32_t bF[2];
                bF[0] = *(const uint32_t*)&VhS[d * STR + kk];
                bF[1] = *(const uint32_t*)&VhS[d * STR + kk + 8];
                mma_f16(O[j], aF, bF);
            }
        }
    }

    // ---- output [B, Lq, H*64] (final Ls in buffer 0 after even #ktiles) ----
    {
        const float* LsF = LsB;
#pragma unroll
        for (int ch = 0; ch < 2; ch++) {
            const int li = sm0g + g + ch * 8;
            const float inv = 1.0f / LsF[li];
            float* op = out + ((size_t)(b * LQ) + l0 + li) * DM + hd * 64 + sn0g;
#pragma unroll
            for (int j = 0; j < 4; j++) {
                float2 o;
                o.x = O[j][ch * 2 + 0] * inv;
                o.y = O[j][ch * 2 + 1] * inv;
                *(float2*)(op + j * 8 + t4 * 2) = o;
            }
        }
    }
}

// =================================================================================
extern "C" void kernel_launch(void* const* d_in, const int* in_sizes, int n_in,
                              void* d_out, int out_size)
{
    const float* hidden   = (const float*)d_in[0];
    const float* q_hidden = (const float*)d_in[1];
    const float* mask     = (const float*)d_in[2];
    const float* Wq       = (const float*)d_in[3];
    const float* bq       = (const float*)d_in[4];
    const float* Wk       = (const float*)d_in[5];
    const float* bk       = (const float*)d_in[6];
    const float* Wv       = (const float*)d_in[7];
    const float* bv       = (const float*)d_in[8];
    const float* dist     = (const float*)d_in[9];
    float* out = (float*)d_out;

    __half *Qp, *Kp, *Vtp, *Ep, *Xq, *Xk, *Wp;
    cudaGetSymbolAddress((void**)&Qp,  g_Q);
    cudaGetSymbolAddress((void**)&Kp,  g_K);
    cudaGetSymbolAddress((void**)&Vtp, g_Vt);
    cudaGetSymbolAddress((void**)&Ep,  g_E);
    cudaGetSymbolAddress((void**)&Xq,  g_Xq);
    cudaGetSymbolAddress((void**)&Xk,  g_Xk);
    cudaGetSymbolAddress((void**)&Wp,  g_W);

    cudaFuncSetAttribute(proj_tc, cudaFuncAttributeMaxDynamicSharedMemorySize,
                         PROJ_SMEM_BYTES);
    cudaFuncSetAttribute(attn_tc, cudaFuncAttributeMaxDynamicSharedMemorySize,
                         ATTN_SMEM);

    const int nq = NB * LQ * DM / 4;
    const int nk = NB * LK * DM / 4;
    const int nw = DM * DM / 4;
    const int ne = (2 * MAXPOS - 1) * DHD / 4;
    const int ntot = nq + nk + 3 * nw + ne;
    convall_kernel<<<(ntot + 255) / 256, 256>>>(
        q_hidden, Xq, nq,
        hidden,   Xk, nk,
        Wq, Wp + 0 * (size_t)DM * DM, nw,
        Wk, Wp + 1 * (size_t)DM * DM, nw,
        Wv, Wp + 2 * (size_t)DM * DM, nw,
        dist, Ep, ne);

    dim3 gq(NB * LQ / 128, DM / 128);
    dim3 gk(NB * LK / 128, DM / 128);
    proj_tc<<<gq, 256, PROJ_SMEM_BYTES>>>(Xq, Wp + 0 * (size_t)DM * DM, bq, Qp,  LQ, 0);
    proj_tc<<<gk, 256, PROJ_SMEM_BYTES>>>(Xk, Wp + 1 * (size_t)DM * DM, bk, Kp,  LK, 0);
    proj_tc<<<gk, 256, PROJ_SMEM_BYTES>>>(Xk, Wp + 2 * (size_t)DM * DM, bv, Vtp, LK, 1);

    dim3 ga(LQ / 64, NH, NB);
    attn_tc<<<ga, 256, ATTN_SMEM>>>(mask, out);
}

// round 16
// speedup vs baseline: 1.3101x; 1.0637x over previous
#include <cuda_runtime.h>
#include <cuda_fp16.h>
#include <math.h>
#include <stdint.h>
#include <string.h>

#define NH   16
#define DHD  64
#define NB   4
#define LQ   1024
#define LK   2048
#define DM   1024
#define MAXPOS 2048
#define STR  72    // fp16 smem row stride (144B)
#define SSTR 136   // S23 fp16 stride

// ---------------- static device scratch ----------------
__device__ __half g_Q[(size_t)NB*NH*LQ*DHD];
__device__ __half g_K[(size_t)NB*NH*LK*DHD];
__device__ __half g_Vt[(size_t)NB*NH*DHD*LK];   // [b,h][d][r]
__device__ __half g_E[(size_t)(2*MAXPOS-1)*DHD];

__device__ __half g_Xq[(size_t)NB*LQ*DM];
__device__ __half g_Xk[(size_t)NB*LK*DM];
__device__ __half g_W[3][(size_t)DM*DM];

// ============================ helpers ============================
__device__ __forceinline__ uint32_t smem_u32(const void* p) {
    uint32_t a;
    asm("{ .reg .u64 t; cvta.to.shared.u64 t, %1; cvt.u32.u64 %0, t; }"
        : "=r"(a) : "l"(p));
    return a;
}
__device__ __forceinline__ void cp_async16(uint32_t saddr, const void* gaddr) {
    asm volatile("cp.async.cg.shared.global [%0], [%1], 16;" :: "r"(saddr), "l"(gaddr));
}
__device__ __forceinline__ void cp_commit() { asm volatile("cp.async.commit_group;"); }
template <int N>
__device__ __forceinline__ void cp_wait() { asm volatile("cp.async.wait_group %0;" :: "n"(N)); }

__device__ __forceinline__ void mma_f16(float* c, const uint32_t* a, const uint32_t* b) {
    asm volatile(
        "mma.sync.aligned.m16n8k16.row.col.f32.f16.f16.f32 "
        "{%0,%1,%2,%3}, {%4,%5,%6,%7}, {%8,%9}, {%0,%1,%2,%3};"
        : "+f"(c[0]), "+f"(c[1]), "+f"(c[2]), "+f"(c[3])
        : "r"(a[0]), "r"(a[1]), "r"(a[2]), "r"(a[3]), "r"(b[0]), "r"(b[1]));
}
__device__ __forceinline__ uint32_t hpack(float x, float y) {
    __half2 h = __floats2half2_rn(x, y);
    uint32_t u; memcpy(&u, &h, 4); return u;
}

// =================================================================================
// Fused fp32->fp16 conversion for all 6 tensors (one launch)
// =================================================================================
__global__ void convall_kernel(
    const float* __restrict__ s0, __half* __restrict__ d0, int n0,
    const float* __restrict__ s1, __half* __restrict__ d1, int n1,
    const float* __restrict__ s2, __half* __restrict__ d2, int n2,
    const float* __restrict__ s3, __half* __restrict__ d3, int n3,
    const float* __restrict__ s4, __half* __restrict__ d4, int n4,
    const float* __restrict__ s5, __half* __restrict__ d5, int n5)
{
    int i = blockIdx.x * blockDim.x + threadIdx.x;
    const float* s; __half* d; int k = i;
    if      (k < n0)                         { s = s0; d = d0; }
    else if ((k -= n0) < n1)                 { s = s1; d = d1; }
    else if ((k -= n1) < n2)                 { s = s2; d = d2; }
    else if ((k -= n2) < n3)                 { s = s3; d = d3; }
    else if ((k -= n3) < n4)                 { s = s4; d = d4; }
    else if ((k -= n4) < n5)                 { s = s5; d = d5; }
    else return;
    float4 v = ((const float4*)s)[k];
    ((uint32_t*)d)[2*k]   = hpack(v.x, v.y);
    ((uint32_t*)d)[2*k+1] = hpack(v.z, v.w);
}

// =================================================================================
// Fused projection GEMM (Q, K, V in one launch; blockIdx.z selects task)
// =================================================================================
#define BK      32
#define KS_STR  40
#define TILE_HF (128 * KS_STR)
#define STAGE_HF (2 * TILE_HF)
#define PROJ_SMEM_BYTES (2 * STAGE_HF * 2)   // 40960 B -> 2 CTAs/SM

__global__ __launch_bounds__(256, 2)
void proj_tc(const __half* __restrict__ Xq_g, const __half* __restrict__ Xk_g,
             const __half* __restrict__ W_g,
             const float* __restrict__ bq, const float* __restrict__ bk,
             const float* __restrict__ bv,
             __half* __restrict__ Qo, __half* __restrict__ Ko, __half* __restrict__ Vo)
{
    const int task = blockIdx.z;
    if (task == 0 && blockIdx.x >= NB * LQ / 128) return;   // Q has half the rows

    const __half* A_g  = (task == 0) ? Xq_g : Xk_g;
    const __half* B_g  = W_g + (size_t)task * DM * DM;
    const float*  bias = (task == 0) ? bq : (task == 1) ? bk : bv;
    __half* outH = (task == 0) ? Qo : (task == 1) ? Ko : Vo;
    const int L    = (task == 0) ? LQ : LK;
    const int mode = (task == 2) ? 1 : 0;

    extern __shared__ __half smem[];
    const uint32_t smem_b = smem_u32(smem);
    const int t = threadIdx.x, lane = t & 31;
    const int wid = t >> 5, g = lane >> 2, t4 = lane & 3;
    const int wm0 = (wid & 3) * 32, wn0 = (wid >> 2) * 64;
    const int m0 = blockIdx.x * 128, n0 = blockIdx.y * 128;
    const int c0 = t * 2;
    const int row0 = c0 >> 2, seg0 = c0 & 3;
    const int row1 = (c0 + 1) >> 2, seg1 = (c0 + 1) & 3;
    const int NS = DM / BK;

    auto load_stage = [&](int kc) {
        const int k0 = kc * BK;
        const uint32_t sb = smem_b + (uint32_t)(kc & 1) * STAGE_HF * 2;
        const uint32_t so0 = (uint32_t)(row0 * KS_STR + seg0 * 8) * 2;
        const uint32_t so1 = (uint32_t)(row1 * KS_STR + seg1 * 8) * 2;
        cp_async16(sb + so0, A_g + (size_t)(m0 + row0) * DM + k0 + seg0 * 8);
        cp_async16(sb + so1, A_g + (size_t)(m0 + row1) * DM + k0 + seg1 * 8);
        cp_async16(sb + TILE_HF * 2 + so0, B_g + (size_t)(n0 + row0) * DM + k0 + seg0 * 8);
        cp_async16(sb + TILE_HF * 2 + so1, B_g + (size_t)(n0 + row1) * DM + k0 + seg1 * 8);
        cp_commit();
    };

    float acc[2][8][4];
#pragma unroll
    for (int i = 0; i < 2; i++)
#pragma unroll
        for (int j = 0; j < 8; j++)
#pragma unroll
            for (int q = 0; q < 4; q++) acc[i][j][q] = 0.0f;

    load_stage(0);
    for (int kc = 0; kc < NS; kc++) {
        if (kc + 1 < NS) { load_stage(kc + 1); cp_wait<1>(); }
        else             { cp_wait<0>(); }
        __syncthreads();
        const __half* sA = smem + (size_t)(kc & 1) * STAGE_HF;
        const __half* sB = sA + TILE_HF;
#pragma unroll
        for (int ks = 0; ks < BK; ks += 16) {
            uint32_t aF[2][4], bF[8][2];
            const int kk = ks + t4 * 2;
#pragma unroll
            for (int i = 0; i < 2; i++) {
                const int r = wm0 + i * 16 + g;
                aF[i][0] = *(const uint32_t*)&sA[r * KS_STR + kk];
                aF[i][1] = *(const uint32_t*)&sA[(r + 8) * KS_STR + kk];
                aF[i][2] = *(const uint32_t*)&sA[r * KS_STR + kk + 8];
                aF[i][3] = *(const uint32_t*)&sA[(r + 8) * KS_STR + kk + 8];
            }
#pragma unroll
            for (int j = 0; j < 8; j++) {
                const int n = wn0 + j * 8 + g;
                bF[j][0] = *(const uint32_t*)&sB[n * KS_STR + kk];
                bF[j][1] = *(const uint32_t*)&sB[n * KS_STR + kk + 8];
            }
#pragma unroll
            for (int i = 0; i < 2; i++)
#pragma unroll
                for (int j = 0; j < 8; j++)
                    mma_f16(acc[i][j], aF[i], bF[j]);
        }
        __syncthreads();
    }
#pragma unroll
    for (int i = 0; i < 2; i++)
#pragma unroll
        for (int j = 0; j < 8; j++) {
            const int cc = n0 + wn0 + j * 8 + t4 * 2;
            const int hh = cc >> 6, dh = cc & 63;
            const float b0 = __ldg(&bias[cc]), b1 = __ldg(&bias[cc + 1]);
#pragma unroll
            for (int rr = 0; rr < 2; rr++) {
                const int r = m0 + wm0 + i * 16 + g + rr * 8;
                const int bidx = r / L, l = r - bidx * L;
                const float f0 = acc[i][j][rr * 2 + 0] + b0;
                const float f1 = acc[i][j][rr * 2 + 1] + b1;
                if (mode == 0) {
                    const size_t base = ((size_t)(bidx * NH + hh) * L + l) * DHD + dh;
                    *(__half2*)&outH[base] = __floats2half2_rn(f0, f1);
                } else {
                    const size_t base = ((size_t)(bidx * NH + hh) * DHD + dh) * LK + l;
                    outH[base] = __float2half(f0);
                    outH[base + LK] = __float2half(f1);
                }
            }
        }
}

// =================================================================================
// Tensor-core attention: 256 threads, 111KB smem -> 2 CTAs/SM (proven R14)
// =================================================================================
#define SM_S23 0
#define SM_QH  34816
#define SM_K0  44032
#define SM_K1  53248
#define SM_V0  62464
#define SM_V1  71680
#define SM_ES  80896
#define SM_MS0 99328
#define SM_MS1 99584
#define SM_PH  99840
#define SM_PM  109056
#define SM_PS  109568
#define SM_MR  110080
#define SM_LS  110592
#define SM_CS  111104
#define ATTN_SMEM 111360

__global__ __launch_bounds__(256, 2)
void attn_tc(const float* __restrict__ mask, float* __restrict__ out)
{
    extern __shared__ char smc[];
    const uint32_t sbu = smem_u32(smc);
    __half* S23 = (__half*)(smc + SM_S23);
    __half* Qh = (__half*)(smc + SM_QH);
    __half* Ph = (__half*)(smc + SM_PH);
    float* Pm = (float*)(smc + SM_PM);
    float* Ps = (float*)(smc + SM_PS);
    float* MrB = (float*)(smc + SM_MR);
    float* LsB = (float*)(smc + SM_LS);
    float* Cs = (float*)(smc + SM_CS);

    const int t = threadIdx.x, lane = t & 31, w = t >> 5;
    const int g = lane >> 2, t4 = lane & 3;
    const int l0 = blockIdx.x * 64, hd = blockIdx.y, b = blockIdx.z;

    const int sm0g = (w & 3) * 16;
    const int sn0g = (w >> 2) * 32;
    const int half = w >> 2;

    const __half* Qg = g_Q + ((size_t)(b * NH + hd) * LQ + l0) * DHD;
    const __half* Kg = g_K + (size_t)(b * NH + hd) * LK * DHD;
    const __half* Vg = g_Vt + (size_t)(b * NH + hd) * DHD * LK;
    const float* mg = mask + (size_t)b * LK;

    for (int c = t; c < 512; c += 256) {
        const int row = c >> 3, cc = c & 7;
        cp_async16(sbu + SM_QH + row * 144 + cc * 16, Qg + row * DHD + cc * 8);
        cp_async16(sbu + SM_K0 + row * 144 + cc * 16, Kg + (size_t)row * DHD + cc * 8);
        cp_async16(sbu + SM_V0 + row * 144 + cc * 16, Vg + (size_t)row * LK + cc * 8);
    }
    {
        const int eb0 = l0 + (MAXPOS - 64);
        for (int c = t; c < 127 * 8; c += 256) {
            const int rw = c >> 3, cc = c & 7;
            cp_async16(sbu + SM_ES + rw * 144 + cc * 16,
                       g_E + (size_t)(eb0 + rw) * DHD + cc * 8);
        }
        if (t < 16) cp_async16(sbu + SM_MS0 + t * 16, mg + t * 4);
        cp_commit();
    }

    if (t < 64) { MrB[t] = -1e30f; LsB[t] = 0.f; }
    if (t < 36) *(uint32_t*)(smc + SM_ES + 127 * 144 + t * 4) = 0u;

    float O[4][4];
#pragma unroll
    for (int j = 0; j < 4; j++)
#pragma unroll
        for (int q = 0; q < 4; q++) O[j][q] = 0.f;

    const bool isQ = (w < 4);
    const int rk    = isQ ? 0 : (w - 4) * 16;
    const int arow0 = isQ ? w * 16 : rk;
    const int band0 = isQ ? w * 16 : 48 - rk;
    const int drow0 = isQ ? w * 16 : 64 + rk;

    const int NT = LK / 64;
    for (int kt = 0; kt < NT; kt++) {
        const int par = kt & 1;
        const char* Kb = smc + (par ? SM_K1 : SM_K0);
        const char* Vb = smc + (par ? SM_V1 : SM_V0);
        const float* MsS = (const float*)(smc + (par ? SM_MS1 : SM_MS0));
        const float* MrC = MrB + par * 64;
        float* MrN = MrB + (par ^ 1) * 64;
        const float* LsC = LsB + par * 64;
        float* LsN = LsB + (par ^ 1) * 64;

        cp_wait<0>();
        __syncthreads();

        if (kt + 1 < NT) {
            const int r1 = (kt + 1) * 64;
            const uint32_t Kp2 = sbu + (par ? SM_K0 : SM_K1);
            const uint32_t Vp2 = sbu + (par ? SM_V0 : SM_V1);
            for (int c = t; c < 512; c += 256) {
                const int row = c >> 3, cc = c & 7;
                cp_async16(Kp2 + row * 144 + cc * 16, Kg + (size_t)(r1 + row) * DHD + cc * 8);
                cp_async16(Vp2 + row * 144 + cc * 16, Vg + (size_t)row * LK + r1 + cc * 8);
            }
            if (t < 16) cp_async16(sbu + (par ? SM_MS0 : SM_MS1) + t * 16, mg + r1 + t * 4);
            cp_commit();
        }

        const __half* KhS = (const __half*)Kb;
        const __half* VhS = (const __half*)Vb;
        const __half* EsS = (const __half*)(smc + SM_ES);

        // ---- GEMM1 (banded, A-frags hoisted) ----
        {
            const __half* Ab = isQ ? Qh : KhS;
            uint32_t aAll[4][4];
#pragma unroll
            for (int k4 = 0; k4 < 4; k4++) {
                const int kk = k4 * 16 + t4 * 2;
                const int r = arow0 + g;
                aAll[k4][0] = *(const uint32_t*)&Ab[r * STR + kk];
                aAll[k4][1] = *(const uint32_t*)&Ab[(r + 8) * STR + kk];
                aAll[k4][2] = *(const uint32_t*)&Ab[r * STR + kk + 8];
                aAll[k4][3] = *(const uint32_t*)&Ab[(r + 8) * STR + kk + 8];
            }
#pragma unroll
            for (int hf = 0; hf < 2; hf++) {
                const int nt0 = band0 / 8 + hf * 5;
                float ea[5][4];
#pragma unroll
                for (int j = 0; j < 5; j++)
#pragma unroll
                    for (int q = 0; q < 4; q++) ea[j][q] = 0.f;
#pragma unroll
                for (int k4 = 0; k4 < 4; k4++) {
                    const int kk = k4 * 16 + t4 * 2;
#pragma unroll
                    for (int j = 0; j < 5; j++) {
                        const int n = (nt0 + j) * 8 + g;
                        uint32_t bf2[2];
                        bf2[0] = *(const uint32_t*)&EsS[n * STR + kk];
                        bf2[1] = *(const uint32_t*)&EsS[n * STR + kk + 8];
                        mma_f16(ea[j], aAll[k4], bf2);
                    }
                }
#pragma unroll
                for (int j = 0; j < 5; j++) {
                    const int m = drow0 + g, n = (nt0 + j) * 8 + t4 * 2;
                    *(uint32_t*)&S23[m * SSTR + n] = hpack(ea[j][0], ea[j][1]);
                    *(uint32_t*)&S23[(m + 8) * SSTR + n] = hpack(ea[j][2], ea[j][3]);
                }
            }
        }
        // ---- GEMM2: Q@K^T ----
        float sc[4][4];
#pragma unroll
        for (int j = 0; j < 4; j++)
#pragma unroll
            for (int q = 0; q < 4; q++) sc[j][q] = 0.f;
#pragma unroll
        for (int k4 = 0; k4 < 4; k4++) {
            const int kk = k4 * 16 + t4 * 2;
            uint32_t aF[4];
            const int r = sm0g + g;
            aF[0] = *(const uint32_t*)&Qh[r * STR + kk];
            aF[1] = *(const uint32_t*)&Qh[(r + 8) * STR + kk];
            aF[2] = *(const uint32_t*)&Qh[r * STR + kk + 8];
            aF[3] = *(const uint32_t*)&Qh[(r + 8) * STR + kk + 8];
#pragma unroll
            for (int j = 0; j < 4; j++) {
                const int n = sn0g + j * 8 + g;
                uint32_t bF[2];
                bF[0] = *(const uint32_t*)&KhS[n * STR + kk];
                bF[1] = *(const uint32_t*)&KhS[n * STR + kk + 8];
                mma_f16(sc[j], aF, bF);
            }
        }
        __syncthreads();   // B2: S23 visible; E reads done

        if (kt + 1 < NT) {
            const int eb1 = l0 - (kt + 1) * 64 + (MAXPOS - 64);
            for (int c = t; c < 127 * 8; c += 256) {
                const int rw = c >> 3, cc = c & 7;
                cp_async16(sbu + SM_ES + rw * 144 + cc * 16,
                           g_E + (size_t)(eb1 + rw) * DHD + cc * 8);
            }
            cp_commit();
        }

        // ---- gather + partial softmax ----
        float mw[2];
#pragma unroll
        for (int ch = 0; ch < 2; ch++) mw[ch] = -1e30f;
#pragma unroll
        for (int j = 0; j < 4; j++) {
            const int ri = sn0g + j * 8 + t4 * 2;
#pragma unroll
            for (int ch = 0; ch < 2; ch++) {
                const int li = sm0g + g + ch * 8;
                const int nn = li - ri + 63;
                float t0 = __half2float(S23[li * SSTR + nn])
                         + __half2float(S23[(64 + ri) * SSTR + nn]);
                float t1 = __half2float(S23[li * SSTR + nn - 1])
                         + __half2float(S23[(65 + ri) * SSTR + nn - 1]);
                float v0 = (sc[j][ch * 2 + 0] + t0) * 0.125f + MsS[ri];
                float v1 = (sc[j][ch * 2 + 1] + t1) * 0.125f + MsS[ri + 1];
                sc[j][ch * 2 + 0] = v0;
                sc[j][ch * 2 + 1] = v1;
                mw[ch] = fmaxf(mw[ch], fmaxf(v0, v1));
            }
        }
#pragma unroll
        for (int ch = 0; ch < 2; ch++) {
            mw[ch] = fmaxf(mw[ch], __shfl_xor_sync(0xffffffffu, mw[ch], 1));
            mw[ch] = fmaxf(mw[ch], __shfl_xor_sync(0xffffffffu, mw[ch], 2));
            float s = 0.f;
#pragma unroll
            for (int j = 0; j < 4; j++) {
                float e0 = __expf(sc[j][ch * 2 + 0] - mw[ch]);
                float e1 = __expf(sc[j][ch * 2 + 1] - mw[ch]);
                sc[j][ch * 2 + 0] = e0;
                sc[j][ch * 2 + 1] = e1;
                s += e0 + e1;
            }
            s += __shfl_xor_sync(0xffffffffu, s, 1);
            s += __shfl_xor_sync(0xffffffffu, s, 2);
            if (t4 == 0) {
                const int row = sm0g + g + ch * 8;
                Pm[row * 2 + half] = mw[ch];
                Ps[row * 2 + half] = s;
            }
        }
        __syncthreads();   // B3

        // ---- finalize ----
#pragma unroll
        for (int ch = 0; ch < 2; ch++) {
            const int row = sm0g + g + ch * 8;
            const float ma = Pm[row * 2], mb2 = Pm[row * 2 + 1];
            const float mold = MrC[row];
            const float mnew = fmaxf(fmaxf(ma, mb2), mold);
            const float f = __expf(mw[ch] - mnew);
#pragma unroll
            for (int j = 0; j < 4; j++) {
                *(uint32_t*)&Ph[row * STR + sn0g + j * 8 + t4 * 2] =
                    hpack(sc[j][ch * 2 + 0] * f, sc[j][ch * 2 + 1] * f);
            }
            if (half == 0 && t4 == 0) {
                const float corr = __expf(mold - mnew);
                const float st = Ps[row * 2] * __expf(ma - mnew)
                               + Ps[row * 2 + 1] * __expf(mb2 - mnew);
                LsN[row] = LsC[row] * corr + st;
                MrN[row] = mnew;
                Cs[row] = corr;
            }
        }
        __syncthreads();   // B4

        // ---- PV ----
        {
            const float c0 = Cs[sm0g + g];
            const float c1 = Cs[sm0g + g + 8];
#pragma unroll
            for (int j = 0; j < 4; j++) {
                O[j][0] *= c0; O[j][1] *= c0;
                O[j][2] *= c1; O[j][3] *= c1;
            }
        }
#pragma unroll
        for (int k4 = 0; k4 < 4; k4++) {
            const int kk = k4 * 16 + t4 * 2;
            uint32_t aF[4];
            const int r = sm0g + g;
            aF[0] = *(const uint32_t*)&Ph[r * STR + kk];
            aF[1] = *(const uint32_t*)&Ph[(r + 8) * STR + kk];
            aF[2] = *(const uint32_t*)&Ph[r * STR + kk + 8];
            aF[3] = *(const uint32_t*)&Ph[(r + 8) * STR + kk + 8];
#pragma unroll
            for (int j = 0; j < 4; j++) {
                const int d = sn0g + j * 8 + g;
                uint32_t bF[2];
                bF[0] = *(const uint32_t*)&VhS[d * STR + kk];
                bF[1] = *(const uint32_t*)&VhS[d * STR + kk + 8];
                mma_f16(O[j], aF, bF);
            }
        }
    }

    // ---- output ----
    {
        const float* LsF = LsB;
#pragma unroll
        for (int ch = 0; ch < 2; ch++) {
            const int li = sm0g + g + ch * 8;
            const float inv = 1.0f / LsF[li];
            float* op = out + ((size_t)(b * LQ) + l0 + li) * DM + hd * 64 + sn0g;
#pragma unroll
            for (int j = 0; j < 4; j++) {
                float2 o;
                o.x = O[j][ch * 2 + 0] * inv;
                o.y = O[j][ch * 2 + 1] * inv;
                *(float2*)(op + j * 8 + t4 * 2) = o;
            }
        }
    }
}

// =================================================================================
extern "C" void kernel_launch(void* const* d_in, const int* in_sizes, int n_in,
                              void* d_out, int out_size)
{
    const float* hidden   = (const float*)d_in[0];
    const float* q_hidden = (const float*)d_in[1];
    const float* mask     = (const float*)d_in[2];
    const float* Wq       = (const float*)d_in[3];
    const float* bq       = (const float*)d_in[4];
    const float* Wk       = (const float*)d_in[5];
    const float* bk       = (const float*)d_in[6];
    const float* Wv       = (const float*)d_in[7];
    const float* bv       = (const float*)d_in[8];
    const float* dist     = (const float*)d_in[9];
    float* out = (float*)d_out;

    __half *Qp, *Kp, *Vtp, *Ep, *Xq, *Xk, *Wp;
    cudaGetSymbolAddress((void**)&Qp,  g_Q);
    cudaGetSymbolAddress((void**)&Kp,  g_K);
    cudaGetSymbolAddress((void**)&Vtp, g_Vt);
    cudaGetSymbolAddress((void**)&Ep,  g_E);
    cudaGetSymbolAddress((void**)&Xq,  g_Xq);
    cudaGetSymbolAddress((void**)&Xk,  g_Xk);
    cudaGetSymbolAddress((void**)&Wp,  g_W);

    cudaFuncSetAttribute(proj_tc, cudaFuncAttributeMaxDynamicSharedMemorySize,
                         PROJ_SMEM_BYTES);
    cudaFuncSetAttribute(attn_tc, cudaFuncAttributeMaxDynamicSharedMemorySize,
                         ATTN_SMEM);

    const int nq = NB * LQ * DM / 4;
    const int nk = NB * LK * DM / 4;
    const int nw = DM * DM / 4;
    const int ne = (2 * MAXPOS - 1) * DHD / 4;
    const int ntot = nq + nk + 3 * nw + ne;
    convall_kernel<<<(ntot + 255) / 256, 256>>>(
        q_hidden, Xq, nq,
        hidden,   Xk, nk,
        Wq, Wp + 0 * (size_t)DM * DM, nw,
        Wk, Wp + 1 * (size_t)DM * DM, nw,
        Wv, Wp + 2 * (size_t)DM * DM, nw,
        dist, Ep, ne);

    // fused Q/K/V projection: grid z = task
    dim3 gp(NB * LK / 128, DM / 128, 3);   // 64 x 8 x 3 (task 0 exits early past 32)
    proj_tc<<<gp, 256, PROJ_SMEM_BYTES>>>(Xq, Xk, Wp, bq, bk, bv, Qp, Kp, Vtp);

    dim3 ga(LQ / 64, NH, NB);
    attn_tc<<<ga, 256, ATTN_SMEM>>>(mask, out);
}